// round 1
// baseline (speedup 1.0000x reference)
#include <cuda_runtime.h>
#include <stdint.h>

#define DIM      64
#define NN_MAX   150000
#define NE_MAX   4000000
#define NLAYERS  3

// ---------------- scratch (device globals; no allocation allowed) ----------------
__device__ int   g_is64;
__device__ int   g_deg[NN_MAX];
__device__ int   g_off[NN_MAX + 1];
__device__ int   g_cur[NN_MAX];
__device__ float g_dinv[NN_MAX];
__device__ int2  g_edges[NE_MAX];               // {src, bitcast(norm)} per edge, CSR by target
__device__ float g_x[(size_t)NN_MAX * DIM];     // ping
__device__ float g_y[(size_t)NN_MAX * DIM];     // pong

// ---------------- dtype detection: int64 vs int32 edge_index ----------------
// If int64: values < 2^31 and nonneg, so every odd 32-bit word of the buffer is 0.
// For int32 data, 128 consecutive odd words all being zero has probability ~0.
__global__ void detect_kernel(const unsigned int* __restrict__ e) {
    int ok64 = 1;
#pragma unroll
    for (int i = 1; i < 256; i += 2) ok64 &= (e[i] == 0u);
    g_is64 = ok64;
}

__global__ void zero_deg_kernel(int n) {
    int i = blockIdx.x * blockDim.x + threadIdx.x;
    if (i < n) g_deg[i] = 0;
}

__global__ void deg_kernel(const void* __restrict__ eidx, int nE) {
    int e = blockIdx.x * blockDim.x + threadIdx.x;
    if (e >= nE) return;
    int c;
    if (g_is64) c = (int)((const long long*)eidx)[(long long)nE + e];
    else        c = ((const int*)eidx)[nE + e];
    atomicAdd(&g_deg[c], 1);
}

__global__ void dinv_kernel(int n) {
    int i = blockIdx.x * blockDim.x + threadIdx.x;
    if (i < n) {
        int d = g_deg[i];
        g_dinv[i] = (d > 0) ? rsqrtf((float)d) : 0.0f;
    }
}

// Single-block exclusive scan of g_deg -> g_off (and copy to g_cur). 150K elems,
// 4 per thread per chunk => 37 chunks of Hillis-Steele; one-time ~tens of us.
__global__ void scan_kernel(int n) {
    __shared__ int sm[1024];
    __shared__ int s_carry;
    int t = threadIdx.x;
    if (t == 0) s_carry = 0;
    __syncthreads();
    for (int base = 0; base < n; base += 4096) {
        int i0 = base + t * 4;
        int v0 = (i0 + 0 < n) ? g_deg[i0 + 0] : 0;
        int v1 = (i0 + 1 < n) ? g_deg[i0 + 1] : 0;
        int v2 = (i0 + 2 < n) ? g_deg[i0 + 2] : 0;
        int v3 = (i0 + 3 < n) ? g_deg[i0 + 3] : 0;
        int s = v0 + v1 + v2 + v3;
        sm[t] = s;
        __syncthreads();
        for (int off = 1; off < 1024; off <<= 1) {
            int val = (t >= off) ? sm[t - off] : 0;
            __syncthreads();
            sm[t] += val;
            __syncthreads();
        }
        int excl = s_carry + sm[t] - s;   // exclusive prefix for this thread's 4 elems
        if (i0 + 0 < n) { g_off[i0 + 0] = excl; g_cur[i0 + 0] = excl; } excl += v0;
        if (i0 + 1 < n) { g_off[i0 + 1] = excl; g_cur[i0 + 1] = excl; } excl += v1;
        if (i0 + 2 < n) { g_off[i0 + 2] = excl; g_cur[i0 + 2] = excl; } excl += v2;
        if (i0 + 3 < n) { g_off[i0 + 3] = excl; g_cur[i0 + 3] = excl; } excl += v3;
        __syncthreads();
        if (t == 1023) s_carry += sm[1023];
        __syncthreads();
    }
    if (t == 0) g_off[n] = s_carry;
}

__global__ void fill_kernel(const void* __restrict__ eidx, int nE) {
    int e = blockIdx.x * blockDim.x + threadIdx.x;
    if (e >= nE) return;
    int r, c;
    if (g_is64) {
        r = (int)((const long long*)eidx)[e];
        c = (int)((const long long*)eidx)[(long long)nE + e];
    } else {
        r = ((const int*)eidx)[e];
        c = ((const int*)eidx)[nE + e];
    }
    float w = g_dinv[r] * g_dinv[c];
    int p = atomicAdd(&g_cur[c], 1);
    g_edges[p] = make_int2(r, __float_as_int(w));
}

// x = concat(user, item); acc(d_out) = 0.25 * x
__global__ void init_kernel(const float4* __restrict__ user,
                            const float4* __restrict__ item,
                            float4* __restrict__ out, int nUser4, int nTot4) {
    int i = blockIdx.x * blockDim.x + threadIdx.x;
    if (i >= nTot4) return;
    float4 v = (i < nUser4) ? user[i] : item[i - nUser4];
    ((float4*)g_x)[i] = v;
    float4 o;
    o.x = 0.25f * v.x; o.y = 0.25f * v.y; o.z = 0.25f * v.z; o.w = 0.25f * v.w;
    out[i] = o;
}

// One warp per target node. lane covers 2 dims (float2): 256B coalesced gather
// per edge, all from an L2-resident x-buffer. Writes y and FMAs 0.25*y into acc.
__global__ void __launch_bounds__(256)
spmm_kernel(int layer, float2* __restrict__ acc, int nNodes) {
    int warp = (blockIdx.x * blockDim.x + threadIdx.x) >> 5;
    if (warp >= nNodes) return;
    int lane = threadIdx.x & 31;

    const float2* __restrict__ xin  = (layer & 1) ? (const float2*)g_y : (const float2*)g_x;
    float2*       __restrict__ yout = (layer & 1) ? (float2*)g_x       : (float2*)g_y;

    int beg = g_off[warp];
    int end = g_off[warp + 1];
    float sx = 0.0f, sy = 0.0f;
#pragma unroll 4
    for (int j = beg; j < end; j++) {
        int2 e = __ldg(&g_edges[j]);
        float w = __int_as_float(e.y);
        float2 v = __ldg(&xin[(size_t)e.x * 32 + lane]);
        sx = fmaf(w, v.x, sx);
        sy = fmaf(w, v.y, sy);
    }
    int o = warp * 32 + lane;
    yout[o] = make_float2(sx, sy);
    float2 a = acc[o];
    a.x = fmaf(0.25f, sx, a.x);
    a.y = fmaf(0.25f, sy, a.y);
    acc[o] = a;
}

extern "C" void kernel_launch(void* const* d_in, const int* in_sizes, int n_in,
                              void* d_out, int out_size) {
    const float* user = (const float*)d_in[0];
    const float* item = (const float*)d_in[1];
    const void*  eidx = d_in[2];

    int nUsers = in_sizes[0] / DIM;
    int nItems = in_sizes[1] / DIM;
    int nNodes = nUsers + nItems;
    int nE     = in_sizes[2] / 2;

    const int T = 256;

    detect_kernel<<<1, 1>>>((const unsigned int*)eidx);
    zero_deg_kernel<<<(nNodes + T - 1) / T, T>>>(nNodes);
    deg_kernel<<<(nE + T - 1) / T, T>>>(eidx, nE);
    dinv_kernel<<<(nNodes + T - 1) / T, T>>>(nNodes);
    scan_kernel<<<1, 1024>>>(nNodes);
    fill_kernel<<<(nE + T - 1) / T, T>>>(eidx, nE);

    int nTot4  = nNodes * DIM / 4;
    int nUser4 = nUsers * DIM / 4;
    init_kernel<<<(nTot4 + T - 1) / T, T>>>((const float4*)user, (const float4*)item,
                                            (float4*)d_out, nUser4, nTot4);

    int spmmBlocks = (nNodes * 32 + T - 1) / T;   // one warp per node
    for (int l = 0; l < NLAYERS; l++)
        spmm_kernel<<<spmmBlocks, T>>>(l, (float2*)d_out, nNodes);
}

// round 2
// speedup vs baseline: 1.6305x; 1.6305x over previous
#include <cuda_runtime.h>
#include <cuda_fp16.h>
#include <stdint.h>

#define DIM      64
#define NN_MAX   150000
#define NE_MAX   4000000
#define NLAYERS  3

// ---------------- scratch (device globals; no allocation allowed) ----------------
__device__ int   g_is64;
__device__ int   g_deg[NN_MAX];
__device__ int   g_off[NN_MAX + 1];
__device__ int   g_cur[NN_MAX];
__device__ int   g_bsum[1024];
__device__ float g_dinv[NN_MAX];
__device__ int   g_esrc[NE_MAX];                      // src per edge, CSR by target
__device__ __align__(128) __half2 g_u0[(size_t)NN_MAX * 32];   // ping (scaled space u = dinv*x)
__device__ __align__(128) __half2 g_u1[(size_t)NN_MAX * 32];   // pong

// ---------------- dtype detection: int64 vs int32 edge_index ----------------
// If int64 (values < 2^31, nonneg): every odd 32-bit word is 0. For int32 data,
// 128 consecutive odd words all being zero has probability ~0.
__global__ void detect_kernel(const unsigned int* __restrict__ e) {
    int ok64 = 1;
#pragma unroll
    for (int i = 1; i < 256; i += 2) ok64 &= (e[i] == 0u);
    g_is64 = ok64;
}

__global__ void zero_deg_kernel(int n) {
    int i = blockIdx.x * blockDim.x + threadIdx.x;
    if (i < n) g_deg[i] = 0;
}

__global__ void deg_kernel(const void* __restrict__ eidx, int nE) {
    int e = blockIdx.x * blockDim.x + threadIdx.x;
    if (e >= nE) return;
    int c;
    if (g_is64) c = (int)((const long long*)eidx)[(long long)nE + e];
    else        c = ((const int*)eidx)[nE + e];
    atomicAdd(&g_deg[c], 1);
}

__global__ void dinv_kernel(int n) {
    int i = blockIdx.x * blockDim.x + threadIdx.x;
    if (i < n) {
        int d = g_deg[i];
        g_dinv[i] = (d > 0) ? rsqrtf((float)d) : 0.0f;
    }
}

// ---------------- full-chip 3-phase exclusive scan of g_deg -> g_off/g_cur ----------------
#define SCAN_B 256
__global__ void scan1_kernel(int n) {            // per-block sums
    __shared__ int sm[SCAN_B];
    int t = threadIdx.x;
    int i = blockIdx.x * SCAN_B + t;
    sm[t] = (i < n) ? g_deg[i] : 0;
    __syncthreads();
    for (int s = SCAN_B / 2; s > 0; s >>= 1) {
        if (t < s) sm[t] += sm[t + s];
        __syncthreads();
    }
    if (t == 0) g_bsum[blockIdx.x] = sm[0];
}

__global__ void scan2_kernel(int nb, int n) {    // 1-block exclusive scan of block sums
    __shared__ int sm[1024];
    int t = threadIdx.x;
    int v = (t < nb) ? g_bsum[t] : 0;
    sm[t] = v;
    __syncthreads();
    for (int off = 1; off < 1024; off <<= 1) {
        int x = (t >= off) ? sm[t - off] : 0;
        __syncthreads();
        sm[t] += x;
        __syncthreads();
    }
    if (t < nb) g_bsum[t] = sm[t] - v;           // exclusive
    if (t == 1023) g_off[n] = sm[1023];          // grand total
}

__global__ void scan3_kernel(int n) {            // per-block exclusive scan + base
    __shared__ int sm[SCAN_B];
    int t = threadIdx.x;
    int i = blockIdx.x * SCAN_B + t;
    int v = (i < n) ? g_deg[i] : 0;
    sm[t] = v;
    __syncthreads();
    for (int off = 1; off < SCAN_B; off <<= 1) {
        int x = (t >= off) ? sm[t - off] : 0;
        __syncthreads();
        sm[t] += x;
        __syncthreads();
    }
    if (i < n) {
        int e = g_bsum[blockIdx.x] + sm[t] - v;
        g_off[i] = e;
        g_cur[i] = e;
    }
}

__global__ void fill_kernel(const void* __restrict__ eidx, int nE) {
    int e = blockIdx.x * blockDim.x + threadIdx.x;
    if (e >= nE) return;
    int r, c;
    if (g_is64) {
        r = (int)((const long long*)eidx)[e];
        c = (int)((const long long*)eidx)[(long long)nE + e];
    } else {
        r = ((const int*)eidx)[e];
        c = ((const int*)eidx)[nE + e];
    }
    int p = atomicAdd(&g_cur[c], 1);
    g_esrc[p] = r;
}

// x0 = concat(user, item); acc(d_out) = 0.25*x0; u0 = dinv*x0 (fp16, scaled space)
__global__ void init_kernel(const float4* __restrict__ user,
                            const float4* __restrict__ item,
                            float4* __restrict__ out, int nUser4, int nTot4) {
    int i = blockIdx.x * blockDim.x + threadIdx.x;
    if (i >= nTot4) return;
    float4 v = (i < nUser4) ? user[i] : item[i - nUser4];
    float4 o;
    o.x = 0.25f * v.x; o.y = 0.25f * v.y; o.z = 0.25f * v.z; o.w = 0.25f * v.w;
    out[i] = o;
    float d = g_dinv[i >> 4];                    // 16 float4 groups per node
    __half2 h0 = __floats2half2_rn(d * v.x, d * v.y);
    __half2 h1 = __floats2half2_rn(d * v.z, d * v.w);
    uint2 p;
    p.x = *(unsigned int*)&h0;
    p.y = *(unsigned int*)&h1;
    ((uint2*)g_u0)[i] = p;
}

// One warp per target node; lane covers 2 dims (half2 => 128B/edge, 1 L2 line).
// s = sum of u[src]; u' = dinv^2 * s; acc += 0.25*dinv*s.
__global__ void __launch_bounds__(256)
spmm_kernel(int layer, float2* __restrict__ acc, int nNodes) {
    int warp = (blockIdx.x * blockDim.x + threadIdx.x) >> 5;
    if (warp >= nNodes) return;
    int lane = threadIdx.x & 31;

    const __half2* __restrict__ xin = (layer & 1) ? g_u1 : g_u0;
    __half2*       __restrict__ uout = (layer & 1) ? g_u0 : g_u1;

    int beg = g_off[warp];
    int end = g_off[warp + 1];
    float sx = 0.0f, sy = 0.0f;
    int j = beg;
    // manual 4x unroll: front-batched independent gathers (MLP=4)
    for (; j + 3 < end; j += 4) {
        int s0 = __ldg(&g_esrc[j + 0]);
        int s1 = __ldg(&g_esrc[j + 1]);
        int s2 = __ldg(&g_esrc[j + 2]);
        int s3 = __ldg(&g_esrc[j + 3]);
        float2 v0 = __half22float2(__ldg(&xin[(size_t)s0 * 32 + lane]));
        float2 v1 = __half22float2(__ldg(&xin[(size_t)s1 * 32 + lane]));
        float2 v2 = __half22float2(__ldg(&xin[(size_t)s2 * 32 + lane]));
        float2 v3 = __half22float2(__ldg(&xin[(size_t)s3 * 32 + lane]));
        sx += (v0.x + v1.x) + (v2.x + v3.x);
        sy += (v0.y + v1.y) + (v2.y + v3.y);
    }
    for (; j < end; j++) {
        int s0 = __ldg(&g_esrc[j]);
        float2 v0 = __half22float2(__ldg(&xin[(size_t)s0 * 32 + lane]));
        sx += v0.x;
        sy += v0.y;
    }

    float dc = g_dinv[warp];
    int o = warp * 32 + lane;
    if (layer != NLAYERS - 1)
        uout[o] = __floats2half2_rn(dc * dc * sx, dc * dc * sy);
    float2 a = acc[o];
    float w = 0.25f * dc;
    a.x = fmaf(w, sx, a.x);
    a.y = fmaf(w, sy, a.y);
    acc[o] = a;
}

extern "C" void kernel_launch(void* const* d_in, const int* in_sizes, int n_in,
                              void* d_out, int out_size) {
    const float* user = (const float*)d_in[0];
    const float* item = (const float*)d_in[1];
    const void*  eidx = d_in[2];

    int nUsers = in_sizes[0] / DIM;
    int nItems = in_sizes[1] / DIM;
    int nNodes = nUsers + nItems;
    int nE     = in_sizes[2] / 2;

    const int T = 256;
    int nScanBlocks = (nNodes + SCAN_B - 1) / SCAN_B;

    detect_kernel<<<1, 1>>>((const unsigned int*)eidx);
    zero_deg_kernel<<<(nNodes + T - 1) / T, T>>>(nNodes);
    deg_kernel<<<(nE + T - 1) / T, T>>>(eidx, nE);
    dinv_kernel<<<(nNodes + T - 1) / T, T>>>(nNodes);
    scan1_kernel<<<nScanBlocks, SCAN_B>>>(nNodes);
    scan2_kernel<<<1, 1024>>>(nScanBlocks, nNodes);
    scan3_kernel<<<nScanBlocks, SCAN_B>>>(nNodes);
    fill_kernel<<<(nE + T - 1) / T, T>>>(eidx, nE);

    int nTot4  = nNodes * DIM / 4;
    int nUser4 = nUsers * DIM / 4;
    init_kernel<<<(nTot4 + T - 1) / T, T>>>((const float4*)user, (const float4*)item,
                                            (float4*)d_out, nUser4, nTot4);

    int spmmBlocks = (nNodes * 32 + T - 1) / T;   // one warp per node
    for (int l = 0; l < NLAYERS; l++)
        spmm_kernel<<<spmmBlocks, T>>>(l, (float2*)d_out, nNodes);
}